// round 3
// baseline (speedup 1.0000x reference)
#include <cuda_runtime.h>
#include <cuda_bf16.h>
#include <math.h>

#define NB    4096
#define NPER  2000
#define HALF  1000                 // hits per warp (2 warps per event)
#define EPB   2                    // events per block
#define WPB   (EPB * 2)            // 4 warps per block
#define THREADS (WPB * 32)         // 128
#define NBLK  (NB / EPB)           // 2048 blocks

// Scratch (no device allocation allowed anywhere).
__device__ double g_part[NBLK];
__device__ unsigned int g_cnt = 0;

#define ACCUM(v)                                   \
    do {                                           \
        acc[0] += (v).x; acc[1] += (v).y;          \
        acc[2] += (v).z; acc[3] += (v).w;          \
        acc[4]  = fmaf((v).x, (v).x, acc[4]);      \
        acc[5]  = fmaf((v).x, (v).y, acc[5]);      \
        acc[6]  = fmaf((v).x, (v).z, acc[6]);      \
        acc[7]  = fmaf((v).x, (v).w, acc[7]);      \
        acc[8]  = fmaf((v).y, (v).y, acc[8]);      \
        acc[9]  = fmaf((v).y, (v).z, acc[9]);      \
        acc[10] = fmaf((v).y, (v).w, acc[10]);     \
        acc[11] = fmaf((v).z, (v).z, acc[11]);     \
        acc[12] = fmaf((v).z, (v).w, acc[12]);     \
        acc[13] = fmaf((v).w, (v).w, acc[13]);     \
    } while (0)

__global__ void __launch_bounds__(THREADS, 12) llfill_fused_kernel(
        const float4* __restrict__ x, float* __restrict__ out) {
    const int lane = threadIdx.x & 31;
    const int warp = threadIdx.x >> 5;          // 0..3
    const int ev   = warp >> 1;                 // event slot within block (0..1)
    const int h    = warp & 1;                  // which half of the event
    const int b    = blockIdx.x * EPB + ev;     // global event index
    const float4* base = x + (size_t)b * NPER + (size_t)h * HALF;

    // 14 accumulators: sums x,y,z,w; second moments xx,xy,xz,xw,yy,yz,yw,zz,zw,ww
    float acc[14];
#pragma unroll
    for (int j = 0; j < 14; j++) acc[j] = 0.0f;

    // 1000 = 31*32 + 8. Main loop: 31 coalesced LDG.128, unroll 8 for MLP.
#pragma unroll 8
    for (int k = 0; k < 31; k++) {
        float4 v = __ldg(base + lane + 32 * k);
        ACCUM(v);
    }
    if (lane < 8) {
        float4 v = __ldg(base + 992 + lane);
        ACCUM(v);
    }

    // Warp-level shuffle reduce of the 14 moments.
#pragma unroll
    for (int j = 0; j < 14; j++) {
        float v = acc[j];
#pragma unroll
        for (int off = 16; off; off >>= 1) v += __shfl_down_sync(0xffffffffu, v, off);
        acc[j] = v;
    }

    // Odd warp hands its partials to the even warp of the same event.
    __shared__ float part[EPB][14];
    __shared__ float spen[EPB];
    if (h == 1 && lane == 0) {
#pragma unroll
        for (int j = 0; j < 14; j++) part[ev][j] = acc[j];
    }
    __syncthreads();

    if (h == 0 && lane == 0) {
#pragma unroll
        for (int j = 0; j < 14; j++) acc[j] += part[ev][j];

        const float invN = 1.0f / (float)NPER;
        const float m0 = acc[0] * invN, m1 = acc[1] * invN;
        const float m2 = acc[2] * invN, m3 = acc[3] * invN;

        float A[4][4];
        A[0][0] = acc[4]  * invN - m0 * m0;
        A[0][1] = A[1][0] = acc[5]  * invN - m0 * m1;
        A[0][2] = A[2][0] = acc[6]  * invN - m0 * m2;
        A[0][3] = A[3][0] = acc[7]  * invN - m0 * m3;
        A[1][1] = acc[8]  * invN - m1 * m1;
        A[1][2] = A[2][1] = acc[9]  * invN - m1 * m2;
        A[1][3] = A[3][1] = acc[10] * invN - m1 * m3;
        A[2][2] = acc[11] * invN - m2 * m2;
        A[2][3] = A[3][2] = acc[12] * invN - m2 * m3;
        A[3][3] = acc[13] * invN - m3 * m3;

        // Shift by trace/4 so fp32 Jacobi works on a small-magnitude matrix.
        const float mu = 0.25f * (A[0][0] + A[1][1] + A[2][2] + A[3][3]);
        A[0][0] -= mu; A[1][1] -= mu; A[2][2] -= mu; A[3][3] -= mu;

        // Cyclic Jacobi, 6 sweeps, fully unrolled (constant indices -> registers).
#pragma unroll
        for (int sweep = 0; sweep < 6; sweep++) {
#pragma unroll
            for (int p = 0; p < 3; p++) {
#pragma unroll
                for (int q = p + 1; q < 4; q++) {
                    float apq = A[p][q];
                    if (fabsf(apq) > 1e-20f) {
                        float theta = (A[q][q] - A[p][p]) * 0.5f / apq;
                        float tt = copysignf(1.0f, theta) /
                                   (fabsf(theta) + sqrtf(fmaf(theta, theta, 1.0f)));
                        float c = rsqrtf(fmaf(tt, tt, 1.0f));
                        float s = tt * c;
                        A[p][p] -= tt * apq;
                        A[q][q] += tt * apq;
                        A[p][q] = 0.0f; A[q][p] = 0.0f;
#pragma unroll
                        for (int k = 0; k < 4; k++) {
                            if (k == p || k == q) continue;
                            float akp = A[k][p], akq = A[k][q];
                            float np = c * akp - s * akq;
                            float nq = s * akp + c * akq;
                            A[k][p] = np; A[p][k] = np;
                            A[k][q] = nq; A[q][k] = nq;
                        }
                    }
                }
            }
        }

        float mn = fminf(fminf(A[0][0], A[1][1]), fminf(A[2][2], A[3][3]));
        float eigmin = mu + mn;                         // min eigenvalue of cov
        float r = mu / (eigmin + 1e-6f) - 1.0f;         // mean(eig) == trace/4 == mu
        spen[ev] = logf(fmaf(r, r, 1.0f));
    }
    __syncthreads();

    // Per-block partial (fixed order -> deterministic), then last-block final reduce.
    __shared__ bool is_last;
    if (threadIdx.x == 0) {
        double s = 0.0;
#pragma unroll
        for (int e = 0; e < EPB; e++) s += (double)spen[e];
        g_part[blockIdx.x] = s;
        __threadfence();
        unsigned int t = atomicInc(&g_cnt, NBLK - 1);   // wraps to 0 -> reusable per launch
        is_last = (t == NBLK - 1);
    }
    __syncthreads();

    if (is_last) {
        // 128 threads reduce 2048 doubles with a fixed tree (deterministic).
        volatile double* vp = g_part;
        const int tid = threadIdx.x;
        double v = 0.0;
#pragma unroll
        for (int i = 0; i < NBLK / THREADS; i++) v += vp[tid + i * THREADS];
#pragma unroll
        for (int off = 16; off; off >>= 1) v += __shfl_down_sync(0xffffffffu, v, off);
        __shared__ double sred[WPB];
        if ((tid & 31) == 0) sred[tid >> 5] = v;
        __syncthreads();
        if (tid == 0) {
            double tot = 0.0;
#pragma unroll
            for (int w = 0; w < WPB; w++) tot += sred[w];
            out[0] = (float)tot;
        }
    }
}

extern "C" void kernel_launch(void* const* d_in, const int* in_sizes, int n_in,
                              void* d_out, int out_size) {
    const float4* x = (const float4*)d_in[0];   // clust_space [B*NPER, 4], 16B rows
    // d_in[1] (batch_idx) is sorted with equal group sizes -> pure reshape, unused.
    llfill_fused_kernel<<<NBLK, THREADS>>>(x, (float*)d_out);
}

// round 4
// speedup vs baseline: 1.1849x; 1.1849x over previous
#include <cuda_runtime.h>
#include <cuda_bf16.h>
#include <math.h>

#define NB   4096
#define NPER 2000
#define WPB  8                    // warps (events) per block
#define THREADS (WPB * 32)
#define NBLK (NB / WPB)           // 512 blocks
#define BATCH 6                   // explicit front-batched LDG.128 per iteration

// Scratch (no device allocation allowed anywhere).
__device__ double g_part[NBLK];
__device__ unsigned int g_cnt = 0;

#define ACCUM(v)                                   \
    do {                                           \
        acc[0] += (v).x; acc[1] += (v).y;          \
        acc[2] += (v).z; acc[3] += (v).w;          \
        acc[4]  = fmaf((v).x, (v).x, acc[4]);      \
        acc[5]  = fmaf((v).x, (v).y, acc[5]);      \
        acc[6]  = fmaf((v).x, (v).z, acc[6]);      \
        acc[7]  = fmaf((v).x, (v).w, acc[7]);      \
        acc[8]  = fmaf((v).y, (v).y, acc[8]);      \
        acc[9]  = fmaf((v).y, (v).z, acc[9]);      \
        acc[10] = fmaf((v).y, (v).w, acc[10]);     \
        acc[11] = fmaf((v).z, (v).z, acc[11]);     \
        acc[12] = fmaf((v).z, (v).w, acc[12]);     \
        acc[13] = fmaf((v).w, (v).w, acc[13]);     \
    } while (0)

__global__ void __launch_bounds__(THREADS, 4) llfill_fused_kernel(
        const float4* __restrict__ x, float* __restrict__ out) {
    const int lane = threadIdx.x & 31;
    const int warp = threadIdx.x >> 5;
    const int b = blockIdx.x * WPB + warp;          // one warp per event
    const float4* base = x + (size_t)b * NPER + lane;

    // 14 accumulators: sums x,y,z,w; second moments xx,xy,xz,xw,yy,yz,yw,zz,zw,ww
    float acc[14];
#pragma unroll
    for (int j = 0; j < 14; j++) acc[j] = 0.0f;

    // 2000 = 62*32 + 16.  62 = 10*BATCH + 2.
    // Explicit batch of BATCH loads into distinct regs -> front-batched LDG.128,
    // guaranteed MLP = BATCH regardless of ptxas scheduling mood.
    float4 v[BATCH];
    for (int kk = 0; kk < 10; kk++) {
        const float4* p = base + (size_t)(32 * BATCH) * kk;
#pragma unroll
        for (int u = 0; u < BATCH; u++) v[u] = __ldg(p + 32 * u);
#pragma unroll
        for (int u = 0; u < BATCH; u++) ACCUM(v[u]);
    }
    {   // iterations 60, 61
        float4 a0 = __ldg(base + 32 * 60);
        float4 a1 = __ldg(base + 32 * 61);
        ACCUM(a0); ACCUM(a1);
    }
    if (lane < 16) {                                // 16-row tail
        float4 a = __ldg(base - lane + 1984 + lane);
        ACCUM(a);
    }

    // Warp-level shuffle reduce of the 14 moments (no smem, no barrier).
#pragma unroll
    for (int j = 0; j < 14; j++) {
        float s = acc[j];
#pragma unroll
        for (int off = 16; off; off >>= 1) s += __shfl_down_sync(0xffffffffu, s, off);
        acc[j] = s;
    }

    __shared__ float spen[WPB];

    if (lane == 0) {
        const float invN = 1.0f / (float)NPER;
        const float m0 = acc[0] * invN, m1 = acc[1] * invN;
        const float m2 = acc[2] * invN, m3 = acc[3] * invN;

        float A[4][4];
        A[0][0] = acc[4]  * invN - m0 * m0;
        A[0][1] = A[1][0] = acc[5]  * invN - m0 * m1;
        A[0][2] = A[2][0] = acc[6]  * invN - m0 * m2;
        A[0][3] = A[3][0] = acc[7]  * invN - m0 * m3;
        A[1][1] = acc[8]  * invN - m1 * m1;
        A[1][2] = A[2][1] = acc[9]  * invN - m1 * m2;
        A[1][3] = A[3][1] = acc[10] * invN - m1 * m3;
        A[2][2] = acc[11] * invN - m2 * m2;
        A[2][3] = A[3][2] = acc[12] * invN - m2 * m3;
        A[3][3] = acc[13] * invN - m3 * m3;

        // Shift by trace/4 so fp32 Jacobi works on a small-magnitude matrix.
        const float mu = 0.25f * (A[0][0] + A[1][1] + A[2][2] + A[3][3]);
        A[0][0] -= mu; A[1][1] -= mu; A[2][2] -= mu; A[3][3] -= mu;

        // Cyclic Jacobi, 6 sweeps, fully unrolled (constant indices -> registers).
#pragma unroll
        for (int sweep = 0; sweep < 6; sweep++) {
#pragma unroll
            for (int p = 0; p < 3; p++) {
#pragma unroll
                for (int q = p + 1; q < 4; q++) {
                    float apq = A[p][q];
                    if (fabsf(apq) > 1e-20f) {
                        float theta = (A[q][q] - A[p][p]) * 0.5f / apq;
                        float tt = copysignf(1.0f, theta) /
                                   (fabsf(theta) + sqrtf(fmaf(theta, theta, 1.0f)));
                        float c = rsqrtf(fmaf(tt, tt, 1.0f));
                        float s = tt * c;
                        A[p][p] -= tt * apq;
                        A[q][q] += tt * apq;
                        A[p][q] = 0.0f; A[q][p] = 0.0f;
#pragma unroll
                        for (int k = 0; k < 4; k++) {
                            if (k == p || k == q) continue;
                            float akp = A[k][p], akq = A[k][q];
                            float np = c * akp - s * akq;
                            float nq = s * akp + c * akq;
                            A[k][p] = np; A[p][k] = np;
                            A[k][q] = nq; A[q][k] = nq;
                        }
                    }
                }
            }
        }

        float mn = fminf(fminf(A[0][0], A[1][1]), fminf(A[2][2], A[3][3]));
        float eigmin = mu + mn;                         // min eigenvalue of cov
        float r = mu / (eigmin + 1e-6f) - 1.0f;         // mean(eig) == trace/4 == mu
        spen[warp] = logf(fmaf(r, r, 1.0f));
    }
    __syncthreads();

    // Per-block partial (fixed order -> deterministic), then last-block final reduce.
    __shared__ bool is_last;
    if (threadIdx.x == 0) {
        double s = 0.0;
#pragma unroll
        for (int w = 0; w < WPB; w++) s += (double)spen[w];
        g_part[blockIdx.x] = s;
        __threadfence();
        unsigned int t = atomicInc(&g_cnt, NBLK - 1);   // wraps to 0 -> reusable per launch
        is_last = (t == NBLK - 1);
    }
    __syncthreads();

    if (is_last) {
        // 256 threads reduce 512 doubles with a fixed tree (deterministic).
        volatile double* vp = g_part;
        const int tid = threadIdx.x;
        double v0 = vp[tid] + vp[tid + THREADS];
#pragma unroll
        for (int off = 16; off; off >>= 1) v0 += __shfl_down_sync(0xffffffffu, v0, off);
        __shared__ double sred[WPB];
        if ((tid & 31) == 0) sred[tid >> 5] = v0;
        __syncthreads();
        if (tid == 0) {
            double tot = 0.0;
#pragma unroll
            for (int w = 0; w < WPB; w++) tot += sred[w];
            out[0] = (float)tot;
        }
    }
}

extern "C" void kernel_launch(void* const* d_in, const int* in_sizes, int n_in,
                              void* d_out, int out_size) {
    const float4* x = (const float4*)d_in[0];   // clust_space [B*NPER, 4], 16B rows
    // d_in[1] (batch_idx) is sorted with equal group sizes -> pure reshape, unused.
    llfill_fused_kernel<<<NBLK, THREADS>>>(x, (float*)d_out);
}

// round 5
// speedup vs baseline: 1.4015x; 1.1828x over previous
#include <cuda_runtime.h>
#include <cuda_bf16.h>
#include <math.h>

#define NB   4096
#define NPER 2000
#define WPB  8                    // warps (events) per block
#define THREADS (WPB * 32)
#define NBLK (NB / WPB)           // 512 blocks
#define BATCH 6                   // explicit front-batched LDG.128 per iteration

// Scratch (no device allocation allowed anywhere).
__device__ double g_part[NBLK];
__device__ unsigned int g_cnt = 0;

#define ACCUM(v)                                   \
    do {                                           \
        acc[0] += (v).x; acc[1] += (v).y;          \
        acc[2] += (v).z; acc[3] += (v).w;          \
        acc[4]  = fmaf((v).x, (v).x, acc[4]);      \
        acc[5]  = fmaf((v).x, (v).y, acc[5]);      \
        acc[6]  = fmaf((v).x, (v).z, acc[6]);      \
        acc[7]  = fmaf((v).x, (v).w, acc[7]);      \
        acc[8]  = fmaf((v).y, (v).y, acc[8]);      \
        acc[9]  = fmaf((v).y, (v).z, acc[9]);      \
        acc[10] = fmaf((v).y, (v).w, acc[10]);     \
        acc[11] = fmaf((v).z, (v).z, acc[11]);     \
        acc[12] = fmaf((v).z, (v).w, acc[12]);     \
        acc[13] = fmaf((v).w, (v).w, acc[13]);     \
    } while (0)

__global__ void __launch_bounds__(THREADS, 4) llfill_fused_kernel(
        const float4* __restrict__ x, float* __restrict__ out) {
    const int lane = threadIdx.x & 31;
    const int warp = threadIdx.x >> 5;
    const int b = blockIdx.x * WPB + warp;          // one warp per event
    const float4* base = x + (size_t)b * NPER + lane;

    // 14 accumulators: sums x,y,z,w; moments xx,xy,xz,xw,yy,yz,yw,zz,zw,ww
    float acc[14];
#pragma unroll
    for (int j = 0; j < 14; j++) acc[j] = 0.0f;

    // 2000 = 62*32 + 16.  62 = 10*BATCH + 2.
    float4 v[BATCH];
    for (int kk = 0; kk < 10; kk++) {
        const float4* p = base + (size_t)(32 * BATCH) * kk;
#pragma unroll
        for (int u = 0; u < BATCH; u++) v[u] = __ldg(p + 32 * u);
#pragma unroll
        for (int u = 0; u < BATCH; u++) ACCUM(v[u]);
    }
    {   // iterations 60, 61
        float4 a0 = __ldg(base + 32 * 60);
        float4 a1 = __ldg(base + 32 * 61);
        ACCUM(a0); ACCUM(a1);
    }
    if (lane < 16) {                                // 16-row tail
        float4 a = __ldg(x + (size_t)b * NPER + 1984 + lane);
        ACCUM(a);
    }

    // Warp shuffle reduce of the 14 moments.
#pragma unroll
    for (int j = 0; j < 14; j++) {
        float s = acc[j];
#pragma unroll
        for (int off = 16; off; off >>= 1) s += __shfl_down_sync(0xffffffffu, s, off);
        acc[j] = s;
    }

    __shared__ float spen[WPB];

    if (lane == 0) {
        const float invN = 1.0f / (float)NPER;
        const float m0 = acc[0] * invN, m1 = acc[1] * invN;
        const float m2 = acc[2] * invN, m3 = acc[3] * invN;

        // Covariance (symmetric), then shift by mu = trace/4 so tr(A)=0.
        float a00 = acc[4]  * invN - m0 * m0;
        float a01 = acc[5]  * invN - m0 * m1;
        float a02 = acc[6]  * invN - m0 * m2;
        float a03 = acc[7]  * invN - m0 * m3;
        float a11 = acc[8]  * invN - m1 * m1;
        float a12 = acc[9]  * invN - m1 * m2;
        float a13 = acc[10] * invN - m1 * m3;
        float a22 = acc[11] * invN - m2 * m2;
        float a23 = acc[12] * invN - m2 * m3;
        float a33 = acc[13] * invN - m3 * m3;

        const float mu = 0.25f * (a00 + a11 + a22 + a33);
        a00 -= mu; a11 -= mu; a22 -= mu; a33 -= mu;

        // p2 = tr(A^2) = sum_ij A_ij^2 (symmetric).
        float offsq = a01*a01 + a02*a02 + a03*a03 + a12*a12 + a13*a13 + a23*a23;
        float p2 = a00*a00 + a11*a11 + a22*a22 + a33*a33 + 2.0f * offsq;

        // B = A^2 (symmetric, 10 entries).
        float b00 = a00*a00 + a01*a01 + a02*a02 + a03*a03;
        float b11 = a01*a01 + a11*a11 + a12*a12 + a13*a13;
        float b22 = a02*a02 + a12*a12 + a22*a22 + a23*a23;
        float b33 = a03*a03 + a13*a13 + a23*a23 + a33*a33;
        float b01 = a00*a01 + a01*a11 + a02*a12 + a03*a13;
        float b02 = a00*a02 + a01*a12 + a02*a22 + a03*a23;
        float b03 = a00*a03 + a01*a13 + a02*a23 + a03*a33;
        float b12 = a01*a02 + a11*a12 + a12*a22 + a13*a23;
        float b13 = a01*a03 + a11*a13 + a12*a23 + a13*a33;
        float b23 = a02*a03 + a12*a13 + a22*a23 + a23*a33;

        // p3 = tr(A^3) = sum_ij B_ij A_ij ; p4 = tr(A^4) = sum_ij B_ij^2.
        float p3 = b00*a00 + b11*a11 + b22*a22 + b33*a33
                 + 2.0f * (b01*a01 + b02*a02 + b03*a03 + b12*a12 + b13*a13 + b23*a23);
        float p4 = b00*b00 + b11*b11 + b22*b22 + b33*b33
                 + 2.0f * (b01*b01 + b02*b02 + b03*b03 + b12*b12 + b13*b13 + b23*b23);

        // Char poly of trace-free A: l^4 + e2 l^2 - e3 l + e4
        // (Newton identities with e1=0).
        float e2 = -0.5f * p2;
        float e3 = p3 * (1.0f / 3.0f);
        float e4 = 0.25f * fmaf(0.5f * p2, p2, -p4);

        // Newton from below the smallest root: all roots real, start
        // l0 = -sqrt(p2) <= lmin (tr=0 => lmin <= 0). Monotone convergence.
        float l = -sqrtf(p2) * 1.000001f - 1e-12f;
#pragma unroll
        for (int it = 0; it < 24; it++) {
            float t  = l * l;
            float pv = fmaf(t + e2, t, fmaf(-e3, l, e4));
            float dv = fmaf(fmaf(4.0f, t, 2.0f * e2), l, -e3);
            l -= __fdividef(pv, dv);
        }

        float eigmin = mu + l;                          // min eigenvalue of cov
        float r = mu / (eigmin + 1e-6f) - 1.0f;         // mean(eig) == trace/4 == mu
        spen[warp] = logf(fmaf(r, r, 1.0f));
    }
    __syncthreads();

    // Per-block partial (fixed order -> deterministic), last-block final reduce.
    __shared__ bool is_last;
    if (threadIdx.x == 0) {
        double s = 0.0;
#pragma unroll
        for (int w = 0; w < WPB; w++) s += (double)spen[w];
        g_part[blockIdx.x] = s;
        __threadfence();
        unsigned int t = atomicInc(&g_cnt, NBLK - 1);   // wraps to 0 each launch
        is_last = (t == NBLK - 1);
    }
    __syncthreads();

    if (is_last) {
        volatile double* vp = g_part;
        const int tid = threadIdx.x;
        double v0 = vp[tid] + vp[tid + THREADS];
#pragma unroll
        for (int off = 16; off; off >>= 1) v0 += __shfl_down_sync(0xffffffffu, v0, off);
        __shared__ double sred[WPB];
        if ((tid & 31) == 0) sred[tid >> 5] = v0;
        __syncthreads();
        if (tid == 0) {
            double tot = 0.0;
#pragma unroll
            for (int w = 0; w < WPB; w++) tot += sred[w];
            out[0] = (float)tot;
        }
    }
}

extern "C" void kernel_launch(void* const* d_in, const int* in_sizes, int n_in,
                              void* d_out, int out_size) {
    const float4* x = (const float4*)d_in[0];   // clust_space [B*NPER, 4], 16B rows
    // d_in[1] (batch_idx) is sorted with equal group sizes -> pure reshape, unused.
    llfill_fused_kernel<<<NBLK, THREADS>>>(x, (float*)d_out);
}

// round 6
// speedup vs baseline: 1.5189x; 1.0837x over previous
#include <cuda_runtime.h>
#include <cuda_bf16.h>
#include <math.h>

#define NB   4096
#define NPER 2000
#define WPB  4                    // warps (events) per block
#define THREADS (WPB * 32)        // 128
#define NBLK (NB / WPB)           // 1024 blocks -> 148*6+136: near-perfect wave balance
#define BATCH 6                   // explicit front-batched LDG.128 per iteration

// Scratch (no device allocation allowed anywhere).
__device__ double g_part[NBLK];
__device__ unsigned int g_cnt = 0;

#define ACCUM(v)                                   \
    do {                                           \
        acc[0] += (v).x; acc[1] += (v).y;          \
        acc[2] += (v).z; acc[3] += (v).w;          \
        acc[4]  = fmaf((v).x, (v).x, acc[4]);      \
        acc[5]  = fmaf((v).x, (v).y, acc[5]);      \
        acc[6]  = fmaf((v).x, (v).z, acc[6]);      \
        acc[7]  = fmaf((v).x, (v).w, acc[7]);      \
        acc[8]  = fmaf((v).y, (v).y, acc[8]);      \
        acc[9]  = fmaf((v).y, (v).z, acc[9]);      \
        acc[10] = fmaf((v).y, (v).w, acc[10]);     \
        acc[11] = fmaf((v).z, (v).z, acc[11]);     \
        acc[12] = fmaf((v).z, (v).w, acc[12]);     \
        acc[13] = fmaf((v).w, (v).w, acc[13]);     \
    } while (0)

__global__ void __launch_bounds__(THREADS, 8) llfill_fused_kernel(
        const float4* __restrict__ x, float* __restrict__ out) {
    const int lane = threadIdx.x & 31;
    const int warp = threadIdx.x >> 5;
    const int b = blockIdx.x * WPB + warp;          // one warp per event
    const float4* base = x + (size_t)b * NPER + lane;

    // 14 accumulators: sums x,y,z,w; moments xx,xy,xz,xw,yy,yz,yw,zz,zw,ww
    float acc[14];
#pragma unroll
    for (int j = 0; j < 14; j++) acc[j] = 0.0f;

    // 2000 = 62*32 + 16.  62 = 10*BATCH + 2.
    float4 v[BATCH];
    for (int kk = 0; kk < 10; kk++) {
        const float4* p = base + (size_t)(32 * BATCH) * kk;
#pragma unroll
        for (int u = 0; u < BATCH; u++) v[u] = __ldg(p + 32 * u);
#pragma unroll
        for (int u = 0; u < BATCH; u++) ACCUM(v[u]);
    }
    {   // iterations 60, 61
        float4 a0 = __ldg(base + 32 * 60);
        float4 a1 = __ldg(base + 32 * 61);
        ACCUM(a0); ACCUM(a1);
    }
    if (lane < 16) {                                // 16-row tail
        float4 a = __ldg(x + (size_t)b * NPER + 1984 + lane);
        ACCUM(a);
    }

    // Warp shuffle reduce of the 14 moments.
#pragma unroll
    for (int j = 0; j < 14; j++) {
        float s = acc[j];
#pragma unroll
        for (int off = 16; off; off >>= 1) s += __shfl_down_sync(0xffffffffu, s, off);
        acc[j] = s;
    }

    __shared__ float spen[WPB];

    if (lane == 0) {
        const float invN = 1.0f / (float)NPER;
        const float m0 = acc[0] * invN, m1 = acc[1] * invN;
        const float m2 = acc[2] * invN, m3 = acc[3] * invN;

        // Covariance (symmetric), then shift by mu = trace/4 so tr(A)=0.
        float a00 = acc[4]  * invN - m0 * m0;
        float a01 = acc[5]  * invN - m0 * m1;
        float a02 = acc[6]  * invN - m0 * m2;
        float a03 = acc[7]  * invN - m0 * m3;
        float a11 = acc[8]  * invN - m1 * m1;
        float a12 = acc[9]  * invN - m1 * m2;
        float a13 = acc[10] * invN - m1 * m3;
        float a22 = acc[11] * invN - m2 * m2;
        float a23 = acc[12] * invN - m2 * m3;
        float a33 = acc[13] * invN - m3 * m3;

        const float mu = 0.25f * (a00 + a11 + a22 + a33);
        a00 -= mu; a11 -= mu; a22 -= mu; a33 -= mu;

        // p2 = tr(A^2) = sum_ij A_ij^2 (symmetric).
        float offsq = a01*a01 + a02*a02 + a03*a03 + a12*a12 + a13*a13 + a23*a23;
        float p2 = a00*a00 + a11*a11 + a22*a22 + a33*a33 + 2.0f * offsq;

        // B = A^2 (symmetric, 10 entries).
        float b00 = a00*a00 + a01*a01 + a02*a02 + a03*a03;
        float b11 = a01*a01 + a11*a11 + a12*a12 + a13*a13;
        float b22 = a02*a02 + a12*a12 + a22*a22 + a23*a23;
        float b33 = a03*a03 + a13*a13 + a23*a23 + a33*a33;
        float b01 = a00*a01 + a01*a11 + a02*a12 + a03*a13;
        float b02 = a00*a02 + a01*a12 + a02*a22 + a03*a23;
        float b03 = a00*a03 + a01*a13 + a02*a23 + a03*a33;
        float b12 = a01*a02 + a11*a12 + a12*a22 + a13*a23;
        float b13 = a01*a03 + a11*a13 + a12*a23 + a13*a33;
        float b23 = a02*a03 + a12*a13 + a22*a23 + a23*a33;

        // p3 = tr(A^3) = sum_ij B_ij A_ij ; p4 = tr(A^4) = sum_ij B_ij^2.
        float p3 = b00*a00 + b11*a11 + b22*a22 + b33*a33
                 + 2.0f * (b01*a01 + b02*a02 + b03*a03 + b12*a12 + b13*a13 + b23*a23);
        float p4 = b00*b00 + b11*b11 + b22*b22 + b33*b33
                 + 2.0f * (b01*b01 + b02*b02 + b03*b03 + b12*b12 + b13*b13 + b23*b23);

        // Char poly of trace-free A: l^4 + e2 l^2 - e3 l + e4 (Newton identities, e1=0).
        float e2 = -0.5f * p2;
        float e3 = p3 * (1.0f / 3.0f);
        float e4 = 0.25f * fmaf(0.5f * p2, p2, -p4);

        // Newton from below the smallest root: all roots real, start
        // l0 = -sqrt(p2) <= lmin (tr=0 => lmin <= 0). Monotone convergence.
        float l = -sqrtf(p2) * 1.000001f - 1e-12f;
#pragma unroll
        for (int it = 0; it < 24; it++) {
            float t  = l * l;
            float pv = fmaf(t + e2, t, fmaf(-e3, l, e4));
            float dv = fmaf(fmaf(4.0f, t, 2.0f * e2), l, -e3);
            l -= __fdividef(pv, dv);
        }

        float eigmin = mu + l;                          // min eigenvalue of cov
        float r = mu / (eigmin + 1e-6f) - 1.0f;         // mean(eig) == trace/4 == mu
        spen[warp] = logf(fmaf(r, r, 1.0f));
    }
    __syncthreads();

    // Per-block partial (fixed order -> deterministic), last-block final reduce.
    __shared__ bool is_last;
    if (threadIdx.x == 0) {
        double s = 0.0;
#pragma unroll
        for (int w = 0; w < WPB; w++) s += (double)spen[w];
        g_part[blockIdx.x] = s;
        __threadfence();
        unsigned int t = atomicInc(&g_cnt, NBLK - 1);   // wraps to 0 each launch
        is_last = (t == NBLK - 1);
    }
    __syncthreads();

    if (is_last) {
        // 128 threads reduce 1024 doubles with a fixed tree (deterministic).
        volatile double* vp = g_part;
        const int tid = threadIdx.x;
        double v0 = 0.0;
#pragma unroll
        for (int i = 0; i < NBLK / THREADS; i++) v0 += vp[tid + i * THREADS];
#pragma unroll
        for (int off = 16; off; off >>= 1) v0 += __shfl_down_sync(0xffffffffu, v0, off);
        __shared__ double sred[WPB];
        if ((tid & 31) == 0) sred[tid >> 5] = v0;
        __syncthreads();
        if (tid == 0) {
            double tot = 0.0;
#pragma unroll
            for (int w = 0; w < WPB; w++) tot += sred[w];
            out[0] = (float)tot;
        }
    }
}

extern "C" void kernel_launch(void* const* d_in, const int* in_sizes, int n_in,
                              void* d_out, int out_size) {
    const float4* x = (const float4*)d_in[0];   // clust_space [B*NPER, 4], 16B rows
    // d_in[1] (batch_idx) is sorted with equal group sizes -> pure reshape, unused.
    llfill_fused_kernel<<<NBLK, THREADS>>>(x, (float*)d_out);
}